// round 5
// baseline (speedup 1.0000x reference)
#include <cuda_runtime.h>
#include <cuda_fp16.h>

#define NN 100000
#define NE 1200000
#define SCAN_B 98   // ceil(NN / 1024)

// ---------------- device scratch (no allocations allowed) ----------------
__device__ int                g_is64;
__device__ int                g_cnt[NN];
__device__ int                g_cur[NN];
__device__ float              g_dinv[NN];
__device__ int                g_rowptr[NN + 1];
__device__ int2               g_edge[NE];          // {src, norm-as-int}
__device__ unsigned long long g_bval[SCAN_B];      // packed (flag<<32 | blocksum)
__device__ __half             g_bufh[NN * 64];     // transformed features (gather operand)
__device__ __half             g_buf2[NN * 64];     // layer-2 transformed features

// packed f32x2 FMA (sm_103a FFMA2; 2x fp32 FMA throughput)
#define FMA_F32X2(d, a, b, c) \
    asm("fma.rn.f32x2 %0, %1, %2, %3;" : "=l"(d) : "l"(a), "l"(b), "l"(c))
#define PACK_F32X2(out, lo, hi) \
    asm("mov.b64 %0, {%1, %2};" : "=l"(out) : "f"(lo), "f"(hi))
#define UNPACK_F32X2(lo, hi, in) \
    asm("mov.b64 {%0, %1}, %2;" : "=f"(lo), "=f"(hi) : "l"(in))

// ---------------- init + dtype probe + flag reset ----------------
__global__ void k_initdetect(const int* __restrict__ raw) {
    __shared__ int flag;
    int i = blockIdx.x * blockDim.x + threadIdx.x;
    if (i < NN) g_cnt[i] = 0;
    if (i < SCAN_B) g_bval[i] = 0ull;
    if (blockIdx.x == 0) {
        if (threadIdx.x == 0) flag = 1;
        __syncthreads();
        if (threadIdx.x < 128) {
            bool ok = (raw[2 * threadIdx.x + 1] == 0) &&
                      ((unsigned)raw[2 * threadIdx.x] < NN);
            if (!ok) atomicAnd(&flag, 0);
        }
        __syncthreads();
        if (threadIdx.x == 0) g_is64 = flag;
    }
}

__device__ __forceinline__ int edge_at(const int* raw, int idx, int is64) {
    return is64 ? (int)((const long long*)raw)[idx] : raw[idx];
}

__global__ void k_count(const int* __restrict__ raw) {
    int e = blockIdx.x * blockDim.x + threadIdx.x;
    if (e >= NE) return;
    int d = edge_at(raw, NE + e, g_is64);
    if ((unsigned)d < NN) atomicAdd(&g_cnt[d], 1);
}

// ---------------- single-kernel scan (all 98 blocks co-resident) ----------------
__global__ void __launch_bounds__(1024) k_scan() {
    __shared__ int wsum[32];
    __shared__ int s_boff;
    int tid = threadIdx.x;
    int lane = tid & 31, wid = tid >> 5;
    int i = blockIdx.x * 1024 + tid;
    int c = (i < NN) ? g_cnt[i] : 0;
    if (i < NN) g_dinv[i] = rsqrtf((float)c + 1.0f);

    // warp-inclusive scan
    int incl = c;
#pragma unroll
    for (int o = 1; o < 32; o <<= 1) {
        int t = __shfl_up_sync(~0u, incl, o);
        if (lane >= o) incl += t;
    }
    if (lane == 31) wsum[wid] = incl;
    __syncthreads();
    if (tid < 32) {
        int w = wsum[tid];
        int iw = w;
#pragma unroll
        for (int o = 1; o < 32; o <<= 1) {
            int t = __shfl_up_sync(~0u, iw, o);
            if (tid >= o) iw += t;
        }
        wsum[tid] = iw - w;                    // exclusive warp offset
        if (tid == 31)                         // publish block aggregate
            atomicExch(&g_bval[blockIdx.x], (1ull << 32) | (unsigned)iw);
    }
    __syncthreads();

    // lookback: warp 0 sums aggregates of all preceding blocks
    if (wid == 0) {
        int my = blockIdx.x;
        unsigned acc = 0;
        for (int base = 0; base < my; base += 32) {
            int j = base + lane;
            if (j < my) {
                unsigned long long v;
                do { v = atomicAdd(&g_bval[j], 0ull); } while ((v >> 32) == 0);
                acc += (unsigned)v;
            }
        }
#pragma unroll
        for (int o = 16; o; o >>= 1) acc += __shfl_down_sync(~0u, acc, o);
        if (lane == 0) s_boff = (int)acc;
    }
    __syncthreads();

    if (i < NN) {
        int excl = incl - c + wsum[wid] + s_boff;
        g_rowptr[i] = excl;
        g_cur[i] = excl;
    }
    if (blockIdx.x == 0 && tid == 0) g_rowptr[NN] = NE;
}

__global__ void k_fill(const int* __restrict__ raw) {
    int e = blockIdx.x * blockDim.x + threadIdx.x;
    if (e >= NE) return;
    int is64 = g_is64;
    int s = edge_at(raw, e, is64);
    int d = edge_at(raw, NE + e, is64);
    if ((unsigned)s >= NN || (unsigned)d >= NN) return;
    int pos = atomicAdd(&g_cur[d], 1);
    g_edge[pos] = make_int2(s, __float_as_int(g_dinv[s] * g_dinv[d]));
}

// ---------------- GEMM1: bufh[N,64] = x[N,64] @ W1[64,64]  (fp32 in, fp16 out) ----------------
__global__ void __launch_bounds__(256) k_gemm1(const float* __restrict__ in,
                                               const float* __restrict__ W,
                                               __half* __restrict__ out) {
    constexpr int TM = 64, XP = 65;
    __shared__ float Ws[64 * 64];
    __shared__ float Xs[TM * XP];
    for (int i = threadIdx.x; i < 64 * 64; i += 256) Ws[i] = W[i];
    int rq = threadIdx.x / 16;     // 16 row groups
    int cg = threadIdx.x % 16;     // 16 col groups of 4
    int ntiles = (NN + TM - 1) / TM;
    for (int tile = blockIdx.x; tile < ntiles; tile += gridDim.x) {
        int row0 = tile * TM;
        int nr = min(TM, NN - row0);
        __syncthreads();
        for (int i = threadIdx.x; i < nr * 64; i += 256)
            Xs[(i >> 6) * XP + (i & 63)] = in[row0 * 64 + i];
        __syncthreads();
        unsigned long long acc[4][2] = {};
#pragma unroll 4
        for (int k = 0; k < 64; k++) {
            ulonglong2 w = *(const ulonglong2*)&Ws[k * 64 + cg * 4];
#pragma unroll
            for (int r = 0; r < 4; r++) {
                float xv = Xs[(rq * 4 + r) * XP + k];
                unsigned long long xx;
                PACK_F32X2(xx, xv, xv);
                FMA_F32X2(acc[r][0], xx, w.x, acc[r][0]);
                FMA_F32X2(acc[r][1], xx, w.y, acc[r][1]);
            }
        }
#pragma unroll
        for (int r = 0; r < 4; r++) {
            int row = row0 + rq * 4 + r;
            if (row < NN) {
                float f0, f1, f2, f3;
                UNPACK_F32X2(f0, f1, acc[r][0]);
                UNPACK_F32X2(f2, f3, acc[r][1]);
                __half* p = &out[row * 64 + cg * 4];
                *(__half2*)p = __floats2half2_rn(f0, f1);
                *(__half2*)(p + 2) = __floats2half2_rn(f2, f3);
            }
        }
    }
}

// ---------------- gather core: warp aggregates one node, lane l -> dims (2l, 2l+1) ----------------
__device__ __forceinline__ float2 gather_node(const __half2* __restrict__ hw,
                                              int node, int lane) {
    float di = g_dinv[node];
    float self = di * di;
    float2 v = __half22float2(__ldg(&hw[node * 32 + lane]));
    float ax = self * v.x, ay = self * v.y;
    int beg = g_rowptr[node], end = g_rowptr[node + 1];
    int j = beg;
    for (; j + 4 <= end; j += 4) {
        int2 e0 = __ldg(&g_edge[j]);
        int2 e1 = __ldg(&g_edge[j + 1]);
        int2 e2 = __ldg(&g_edge[j + 2]);
        int2 e3 = __ldg(&g_edge[j + 3]);
        float2 u0 = __half22float2(__ldg(&hw[e0.x * 32 + lane]));
        float2 u1 = __half22float2(__ldg(&hw[e1.x * 32 + lane]));
        float2 u2 = __half22float2(__ldg(&hw[e2.x * 32 + lane]));
        float2 u3 = __half22float2(__ldg(&hw[e3.x * 32 + lane]));
        float w0 = __int_as_float(e0.y), w1 = __int_as_float(e1.y);
        float w2 = __int_as_float(e2.y), w3 = __int_as_float(e3.y);
        ax = fmaf(w0, u0.x, ax); ay = fmaf(w0, u0.y, ay);
        ax = fmaf(w1, u1.x, ax); ay = fmaf(w1, u1.y, ay);
        ax = fmaf(w2, u2.x, ax); ay = fmaf(w2, u2.y, ay);
        ax = fmaf(w3, u3.x, ax); ay = fmaf(w3, u3.y, ay);
    }
    for (; j < end; j++) {
        int2 e = __ldg(&g_edge[j]);
        float2 u = __half22float2(__ldg(&hw[e.x * 32 + lane]));
        float w = __int_as_float(e.y);
        ax = fmaf(w, u.x, ax); ay = fmaf(w, u.y, ay);
    }
    return make_float2(ax, ay);
}

// ---------------- fused A: h1 = relu(agg(bufh)+b1); buf2 = h1 @ W2 ----------------
__global__ void __launch_bounds__(256) k_gather_mm64(const __half2* __restrict__ hw,
                                                     const float* __restrict__ bias,
                                                     const float* __restrict__ W,
                                                     __half2* __restrict__ out) {
    __shared__ unsigned long long Ws[64 * 32];   // W[64][64] as packed float2
    for (int i = threadIdx.x; i < 64 * 32; i += 256)
        Ws[i] = ((const unsigned long long*)W)[i];
    __syncthreads();
    int lane = threadIdx.x & 31;
    int warp = blockIdx.x * 8 + (threadIdx.x >> 5);
    int nwarps = gridDim.x * 8;
    float2 b = ((const float2*)bias)[lane];

    for (int node = warp; node < NN; node += nwarps) {
        float2 h = gather_node(hw, node, lane);
        float ax = fmaxf(h.x + b.x, 0.f);
        float ay = fmaxf(h.y + b.y, 0.f);
        // out[2l],out[2l+1] = sum_k h[k]*W[k][2l..2l+1]  via warp shuffles
        unsigned long long acc0 = 0ull, acc1 = 0ull;
#pragma unroll
        for (int kk = 0; kk < 32; kk++) {
            float hx = __shfl_sync(~0u, ax, kk);   // h[2kk]
            float hy = __shfl_sync(~0u, ay, kk);   // h[2kk+1]
            unsigned long long w0 = Ws[(2 * kk) * 32 + lane];
            unsigned long long w1 = Ws[(2 * kk + 1) * 32 + lane];
            unsigned long long xx, yy;
            PACK_F32X2(xx, hx, hx);
            PACK_F32X2(yy, hy, hy);
            FMA_F32X2(acc0, xx, w0, acc0);
            FMA_F32X2(acc1, yy, w1, acc1);
        }
        float s0, s1, t0, t1;
        UNPACK_F32X2(s0, s1, acc0);
        UNPACK_F32X2(t0, t1, acc1);
        out[node * 32 + lane] = __floats2half2_rn(s0 + t0, s1 + t1);
    }
}

// ---------------- fused B: h2 = relu(agg(buf2)+b2); out = h2 @ Wl + bl  (fp32) ----------------
__global__ void __launch_bounds__(256) k_gather_mm32(const __half2* __restrict__ hw,
                                                     const float* __restrict__ bias,
                                                     const float* __restrict__ W,
                                                     const float* __restrict__ bl,
                                                     float* __restrict__ out) {
    __shared__ float Ws[64 * 32];                // W[64][32]
    for (int i = threadIdx.x; i < 64 * 32; i += 256) Ws[i] = W[i];
    __syncthreads();
    int lane = threadIdx.x & 31;
    int warp = blockIdx.x * 8 + (threadIdx.x >> 5);
    int nwarps = gridDim.x * 8;
    float2 b = ((const float2*)bias)[lane];
    float blv = bl[lane];

    for (int node = warp; node < NN; node += nwarps) {
        float2 h = gather_node(hw, node, lane);
        float ax = fmaxf(h.x + b.x, 0.f);
        float ay = fmaxf(h.y + b.y, 0.f);
        float acc0 = 0.f, acc1 = 0.f;            // two chains for ILP
#pragma unroll
        for (int kk = 0; kk < 32; kk++) {
            float hx = __shfl_sync(~0u, ax, kk);   // h[2kk]
            float hy = __shfl_sync(~0u, ay, kk);   // h[2kk+1]
            acc0 = fmaf(hx, Ws[(2 * kk) * 32 + lane], acc0);
            acc1 = fmaf(hy, Ws[(2 * kk + 1) * 32 + lane], acc1);
        }
        out[node * 32 + lane] = acc0 + acc1 + blv;
    }
}

// ---------------- launch ----------------
extern "C" void kernel_launch(void* const* d_in, const int* in_sizes, int n_in,
                              void* d_out, int out_size) {
    const float* x  = (const float*)d_in[0];
    const int*   ei = (const int*)d_in[1];
    const float* W1 = (const float*)d_in[2];
    const float* b1 = (const float*)d_in[3];
    const float* W2 = (const float*)d_in[4];
    const float* b2 = (const float*)d_in[5];
    const float* Wl = (const float*)d_in[6];
    const float* bl = (const float*)d_in[7];
    float*       out = (float*)d_out;

    __half* bufh; cudaGetSymbolAddress((void**)&bufh, g_bufh);
    __half* buf2; cudaGetSymbolAddress((void**)&buf2, g_buf2);

    static cudaStream_t s2 = nullptr;
    static cudaEvent_t evFork = nullptr, evJoin = nullptr;
    if (s2 == nullptr) {
        cudaStreamCreateWithFlags(&s2, cudaStreamNonBlocking);
        cudaEventCreateWithFlags(&evFork, cudaEventDisableTiming);
        cudaEventCreateWithFlags(&evJoin, cudaEventDisableTiming);
    }

    const int TB = 256;
    int gN = (NN + TB - 1) / TB;
    int gE = (NE + TB - 1) / TB;
    const int FUSED_GRID = 592;    // 4 blocks/SM

    // fork: GEMM1 independent of CSR build
    cudaEventRecord(evFork, 0);
    cudaStreamWaitEvent(s2, evFork, 0);
    k_gemm1<<<296, 256, 0, s2>>>(x, W1, bufh);
    cudaEventRecord(evJoin, s2);

    // CSR build (concurrent with GEMM1)
    k_initdetect<<<gN, TB>>>(ei);
    k_count<<<gE, TB>>>(ei);
    k_scan<<<SCAN_B, 1024>>>();
    k_fill<<<gE, TB>>>(ei);

    // join, then two fused layers
    cudaStreamWaitEvent(0, evJoin, 0);
    k_gather_mm64<<<FUSED_GRID, 256>>>((const __half2*)bufh, b1, W2, (__half2*)buf2);
    k_gather_mm32<<<FUSED_GRID, 256>>>((const __half2*)buf2, b2, Wl, bl, out);
}

// round 6
// speedup vs baseline: 1.3651x; 1.3651x over previous
#include <cuda_runtime.h>
#include <cuda_fp16.h>

#define NN 100000
#define NE 1200000
#define SCAN_B 98   // ceil(NN / 1024)

// ---------------- device scratch (no allocations allowed) ----------------
// NOTE: g_cnt and g_bval are zero at module load; k_scan re-zeroes g_cnt and
// k_fill re-zeroes g_bval each call, so every replay starts from clean state.
__device__ int                g_cnt[NN];
__device__ int                g_cur[NN];
__device__ float              g_dinv[NN];
__device__ int                g_rowptr[NN + 1];
__device__ int2               g_edge[NE];          // {src, norm-as-int}
__device__ unsigned long long g_bval[SCAN_B];      // packed (flag<<32 | blocksum)
__device__ __half             g_bufh[NN * 64];     // transformed features (gather operand)
__device__ __half             g_buf2[NN * 64];     // aggregated hidden state

// packed f32x2 FMA (sm_103a FFMA2; 2x fp32 FMA throughput)
#define FMA_F32X2(d, a, b, c) \
    asm("fma.rn.f32x2 %0, %1, %2, %3;" : "=l"(d) : "l"(a), "l"(b), "l"(c))
#define PACK_F32X2(out, lo, hi) \
    asm("mov.b64 %0, {%1, %2};" : "=l"(out) : "f"(lo), "f"(hi))
#define UNPACK_F32X2(lo, hi, in) \
    asm("mov.b64 {%0, %1}, %2;" : "=f"(lo), "=f"(hi) : "l"(in))

// ---------------- per-block dtype probe (first 128 values, L2-hit) ----------------
__device__ __forceinline__ int probe_is64(const int* __restrict__ raw) {
    __shared__ int s_is64;
    if (threadIdx.x < 32) {
        bool ok = true;
#pragma unroll
        for (int k = 0; k < 4; k++) {
            int idx = threadIdx.x * 4 + k;
            ok &= (raw[2 * idx + 1] == 0) && ((unsigned)raw[2 * idx] < NN);
        }
        unsigned m = __ballot_sync(~0u, ok);
        if (threadIdx.x == 0) s_is64 = (m == ~0u) ? 1 : 0;
    }
    __syncthreads();
    return s_is64;
}

__device__ __forceinline__ int edge_at(const int* raw, int idx, int is64) {
    return is64 ? (int)((const long long*)raw)[idx] : raw[idx];
}

// ---------------- count (no predecessors; g_cnt pre-zeroed by prior scan) ----------------
__global__ void k_count(const int* __restrict__ raw) {
    int is64 = probe_is64(raw);
    int e = blockIdx.x * blockDim.x + threadIdx.x;
    if (e >= NE) return;
    int d = edge_at(raw, NE + e, is64);
    if ((unsigned)d < NN) atomicAdd(&g_cnt[d], 1);
}

// ---------------- single-kernel scan (98 blocks co-resident, decoupled lookback) ----
__global__ void __launch_bounds__(1024) k_scan() {
    __shared__ int wsum[32];
    __shared__ int s_boff;
    int tid = threadIdx.x;
    int lane = tid & 31, wid = tid >> 5;
    int i = blockIdx.x * 1024 + tid;
    int c = (i < NN) ? g_cnt[i] : 0;
    if (i < NN) {
        g_dinv[i] = rsqrtf((float)c + 1.0f);
        g_cnt[i] = 0;                          // reset for next replay
    }

    int incl = c;
#pragma unroll
    for (int o = 1; o < 32; o <<= 1) {
        int t = __shfl_up_sync(~0u, incl, o);
        if (lane >= o) incl += t;
    }
    if (lane == 31) wsum[wid] = incl;
    __syncthreads();
    if (tid < 32) {
        int w = wsum[tid];
        int iw = w;
#pragma unroll
        for (int o = 1; o < 32; o <<= 1) {
            int t = __shfl_up_sync(~0u, iw, o);
            if (tid >= o) iw += t;
        }
        wsum[tid] = iw - w;                    // exclusive warp offset
        if (tid == 31)                         // publish block aggregate
            atomicExch(&g_bval[blockIdx.x], (1ull << 32) | (unsigned)iw);
    }
    __syncthreads();

    if (wid == 0) {
        int my = blockIdx.x;
        unsigned acc = 0;
        for (int base = 0; base < my; base += 32) {
            int j = base + lane;
            if (j < my) {
                unsigned long long v;
                do { v = atomicAdd(&g_bval[j], 0ull); } while ((v >> 32) == 0);
                acc += (unsigned)v;
            }
        }
#pragma unroll
        for (int o = 16; o; o >>= 1) acc += __shfl_down_sync(~0u, acc, o);
        if (lane == 0) s_boff = (int)acc;
    }
    __syncthreads();

    if (i < NN) {
        int excl = incl - c + wsum[wid] + s_boff;
        g_rowptr[i] = excl;
        g_cur[i] = excl;
    }
    if (blockIdx.x == 0 && tid == 0) g_rowptr[NN] = NE;
}

// ---------------- fill CSR (also resets g_bval flags for next replay) ----------------
__global__ void k_fill(const int* __restrict__ raw) {
    int is64 = probe_is64(raw);
    if (blockIdx.x == 0 && threadIdx.x < SCAN_B) g_bval[threadIdx.x] = 0ull;
    int e = blockIdx.x * blockDim.x + threadIdx.x;
    if (e >= NE) return;
    int s = edge_at(raw, e, is64);
    int d = edge_at(raw, NE + e, is64);
    if ((unsigned)s >= NN || (unsigned)d >= NN) return;
    int pos = atomicAdd(&g_cur[d], 1);
    g_edge[pos] = make_int2(s, __float_as_int(g_dinv[s] * g_dinv[d]));
}

// ---------------- GEMM epilogue stores ----------------
__device__ __forceinline__ void store4(float* p, float a, float b, float c, float d) {
    *(float4*)p = make_float4(a, b, c, d);
}
__device__ __forceinline__ void store4(__half* p, float a, float b, float c, float d) {
    *(__half2*)p = __floats2half2_rn(a, b);
    *(__half2*)(p + 2) = __floats2half2_rn(c, d);
}

// ---------------- dense GEMM: out[N,NC] = in[N,64] @ W[64,NC] (+bias) ----------------
template <int NC, typename InT, typename OutT, bool BIAS>
__global__ void __launch_bounds__(256) k_gemm(const InT* __restrict__ in,
                                              const float* __restrict__ W,
                                              const float* __restrict__ bias,
                                              OutT* __restrict__ out) {
    constexpr int CG = NC / 4;
    constexpr int RQ = 256 / CG;
    constexpr int TM = RQ * 4;
    constexpr int XP = 65;
    __shared__ float Ws[64 * NC];
    __shared__ float Xs[TM * XP];

    for (int i = threadIdx.x; i < 64 * NC; i += 256) Ws[i] = W[i];

    int rq = threadIdx.x / CG;
    int cg = threadIdx.x % CG;
    int ntiles = (NN + TM - 1) / TM;

    for (int tile = blockIdx.x; tile < ntiles; tile += gridDim.x) {
        int row0 = tile * TM;
        int nr = min(TM, NN - row0);
        __syncthreads();
        if constexpr (sizeof(InT) == 4) {
            const float* src = (const float*)in + row0 * 64;
            for (int i = threadIdx.x; i < nr * 64; i += 256)
                Xs[(i >> 6) * XP + (i & 63)] = src[i];
        } else {
            const __half2* src = (const __half2*)((const __half*)in + row0 * 64);
            for (int i = threadIdx.x; i < nr * 32; i += 256) {
                float2 f = __half22float2(src[i]);
                int r = i >> 5, c = (i & 31) * 2;
                Xs[r * XP + c] = f.x;
                Xs[r * XP + c + 1] = f.y;
            }
        }
        __syncthreads();

        unsigned long long acc[4][2] = {};
#pragma unroll 4
        for (int k = 0; k < 64; k++) {
            ulonglong2 w = *(const ulonglong2*)&Ws[k * NC + cg * 4];
#pragma unroll
            for (int r = 0; r < 4; r++) {
                float xv = Xs[(rq * 4 + r) * XP + k];
                unsigned long long xx;
                PACK_F32X2(xx, xv, xv);
                FMA_F32X2(acc[r][0], xx, w.x, acc[r][0]);
                FMA_F32X2(acc[r][1], xx, w.y, acc[r][1]);
            }
        }
        float4 bv = make_float4(0.f, 0.f, 0.f, 0.f);
        if (BIAS) bv = *(const float4*)&bias[cg * 4];
#pragma unroll
        for (int r = 0; r < 4; r++) {
            int row = row0 + rq * 4 + r;
            if (row < NN) {
                float f0, f1, f2, f3;
                UNPACK_F32X2(f0, f1, acc[r][0]);
                UNPACK_F32X2(f2, f3, acc[r][1]);
                store4(&out[row * NC + cg * 4],
                       f0 + bv.x, f1 + bv.y, f2 + bv.z, f3 + bv.w);
            }
        }
    }
}

// ---------------- aggregate: out[i] = relu( sum_e norm*hw[src] + dinv^2*hw[i] + b ) ----------------
__global__ void __launch_bounds__(256) k_gather(const __half2* __restrict__ hw,
                                                const float* __restrict__ bias,
                                                __half2* __restrict__ hout) {
    int node = blockIdx.x * 8 + (threadIdx.x >> 5);
    if (node >= NN) return;
    int lane = threadIdx.x & 31;

    float di = g_dinv[node];
    float self = di * di;
    float2 v = __half22float2(__ldg(&hw[node * 32 + lane]));
    float ax = self * v.x, ay = self * v.y;

    int beg = g_rowptr[node], end = g_rowptr[node + 1];
    int j = beg;
    for (; j + 4 <= end; j += 4) {
        int2 e0 = __ldg(&g_edge[j]);
        int2 e1 = __ldg(&g_edge[j + 1]);
        int2 e2 = __ldg(&g_edge[j + 2]);
        int2 e3 = __ldg(&g_edge[j + 3]);
        float2 u0 = __half22float2(__ldg(&hw[e0.x * 32 + lane]));
        float2 u1 = __half22float2(__ldg(&hw[e1.x * 32 + lane]));
        float2 u2 = __half22float2(__ldg(&hw[e2.x * 32 + lane]));
        float2 u3 = __half22float2(__ldg(&hw[e3.x * 32 + lane]));
        float w0 = __int_as_float(e0.y), w1 = __int_as_float(e1.y);
        float w2 = __int_as_float(e2.y), w3 = __int_as_float(e3.y);
        ax = fmaf(w0, u0.x, ax); ay = fmaf(w0, u0.y, ay);
        ax = fmaf(w1, u1.x, ax); ay = fmaf(w1, u1.y, ay);
        ax = fmaf(w2, u2.x, ax); ay = fmaf(w2, u2.y, ay);
        ax = fmaf(w3, u3.x, ax); ay = fmaf(w3, u3.y, ay);
    }
    for (; j < end; j++) {
        int2 e = __ldg(&g_edge[j]);
        float2 u = __half22float2(__ldg(&hw[e.x * 32 + lane]));
        float w = __int_as_float(e.y);
        ax = fmaf(w, u.x, ax); ay = fmaf(w, u.y, ay);
    }
    float2 b = ((const float2*)bias)[lane];
    ax = fmaxf(ax + b.x, 0.f);
    ay = fmaxf(ay + b.y, 0.f);
    hout[node * 32 + lane] = __floats2half2_rn(ax, ay);
}

// ---------------- launch ----------------
extern "C" void kernel_launch(void* const* d_in, const int* in_sizes, int n_in,
                              void* d_out, int out_size) {
    const float* x  = (const float*)d_in[0];
    const int*   ei = (const int*)d_in[1];
    const float* W1 = (const float*)d_in[2];
    const float* b1 = (const float*)d_in[3];
    const float* W2 = (const float*)d_in[4];
    const float* b2 = (const float*)d_in[5];
    const float* Wl = (const float*)d_in[6];
    const float* bl = (const float*)d_in[7];
    float*       out = (float*)d_out;

    __half* bufh; cudaGetSymbolAddress((void**)&bufh, g_bufh);
    __half* buf2; cudaGetSymbolAddress((void**)&buf2, g_buf2);

    static cudaStream_t s2 = nullptr;
    static cudaEvent_t evFork = nullptr, evJoin = nullptr;
    if (s2 == nullptr) {
        cudaStreamCreateWithFlags(&s2, cudaStreamNonBlocking);
        cudaEventCreateWithFlags(&evFork, cudaEventDisableTiming);
        cudaEventCreateWithFlags(&evJoin, cudaEventDisableTiming);
    }

    const int TB = 256;
    int gE = (NE + TB - 1) / TB;
    const int GEMM_GRID = 296;
    const int GATHER_GRID = (NN + 7) / 8;

    // fork: GEMM1 (x @ W1) fully independent of the CSR build
    cudaEventRecord(evFork, 0);
    cudaStreamWaitEvent(s2, evFork, 0);
    k_gemm<64, float, __half, false><<<GEMM_GRID, 256, 0, s2>>>(x, W1, nullptr, bufh);
    cudaEventRecord(evJoin, s2);

    // CSR build (concurrent with GEMM1); count has no predecessors
    k_count<<<gE, TB>>>(ei);
    k_scan<<<SCAN_B, 1024>>>();
    k_fill<<<gE, TB>>>(ei);

    // join, then alternate gather / GEMM
    cudaStreamWaitEvent(0, evJoin, 0);
    k_gather<<<GATHER_GRID, 256>>>((const __half2*)bufh, b1, (__half2*)buf2);
    k_gemm<64, __half, __half, false><<<GEMM_GRID, 256>>>(buf2, W2, nullptr, bufh);
    k_gather<<<GATHER_GRID, 256>>>((const __half2*)bufh, b2, (__half2*)buf2);
    k_gemm<32, __half, float, true><<<GEMM_GRID, 256>>>(buf2, Wl, bl, out);
}